// round 10
// baseline (speedup 1.0000x reference)
#include <cuda_runtime.h>
#include <cstdint>
#include <cstddef>

// Problem dims (fixed by the dataset)
#define B_ 64
#define S_ 1024
#define I_ 512
#define H_ 1024
#define O_ 512

typedef unsigned long long ull;

// ---------------- scratch (no cudaMalloc allowed) ----------------
__device__ float g_xp[(size_t)B_ * S_ * H_];  // x-projection (B*S, H)
__device__ float g_hs[(size_t)B_ * S_ * H_];  // hidden states [b][s][H]
__device__ unsigned g_bar8[8 * 32];           // 8 padded barrier counters

// ---------------- helpers ----------------
__device__ __forceinline__ ull fma2(ull a, ull b, ull c) {
    ull d;
    asm("fma.rn.f32x2 %0, %1, %2, %3;" : "=l"(d) : "l"(a), "l"(b), "l"(c));
    return d;
}
__device__ __forceinline__ ull add2(ull a, ull b) {
    ull d;
    asm("add.rn.f32x2 %0, %1, %2;" : "=l"(d) : "l"(a), "l"(b));
    return d;
}
__device__ __forceinline__ ull pack2(float x, float y) {
    ull d; asm("mov.b64 %0, {%1, %2};" : "=l"(d) : "f"(x), "f"(y)); return d;
}
__device__ __forceinline__ void unpack2(ull v, float& lo, float& hi) {
    asm("mov.b64 {%0, %1}, %2;" : "=f"(lo), "=f"(hi) : "l"(v));
}
__device__ __forceinline__ uint32_t smem_u32(const void* p) {
    uint32_t a;
    asm("{ .reg .u64 t; cvta.to.shared.u64 t, %1; cvt.u32.u64 %0, t; }"
        : "=r"(a) : "l"(p));
    return a;
}
__device__ __forceinline__ void cp16(uint32_t saddr, const void* g) {
    asm volatile("cp.async.cg.shared.global [%0], [%1], 16;" :: "r"(saddr), "l"(g));
}
#define CP_COMMIT() asm volatile("cp.async.commit_group;" ::: "memory")
#define CP_WAIT(n)  asm volatile("cp.async.wait_group %0;" :: "n"(n) : "memory")

// Accurate tanh, robust under --use_fast_math.
__device__ __forceinline__ float tanh_acc(float x) {
    float ax = fabsf(x);
    float e  = __expf(-2.0f * ax);
    float r  = (1.0f - e) / (1.0f + e);
    return copysignf(r, x);
}

__global__ void zero_bar() {
    if (threadIdx.x < 8 * 32) g_bar8[threadIdx.x] = 0u;
}

// ---------------- NT GEMM with f32x2 FMA ----------------
__global__ void __launch_bounds__(256)
gemm_nt_bias(const float* __restrict__ A, const float* __restrict__ Bm,
             const float* __restrict__ bias0, const float* __restrict__ bias1,
             float* __restrict__ C, int M, int N, int K)
{
    const int BK = 16;
    __shared__ float As[16][128 + 4];
    __shared__ float Bs[16][128 + 4];

    int t  = threadIdx.x;
    int tx = t & 15;
    int ty = t >> 4;
    int bm = blockIdx.y * 128;
    int bn = blockIdx.x * 128;

    ull acc2[8][4];
#pragma unroll
    for (int i = 0; i < 8; i++)
#pragma unroll
        for (int j = 0; j < 4; j++) acc2[i][j] = 0ull;

    for (int kc = 0; kc < K; kc += BK) {
#pragma unroll
        for (int i = 0; i < 2; i++) {
            int id = t + i * 256;
            int r  = id >> 2;
            int c4 = id & 3;
            float4 va = *(const float4*)(A  + (size_t)(bm + r) * K + kc + c4 * 4);
            As[c4 * 4 + 0][r] = va.x; As[c4 * 4 + 1][r] = va.y;
            As[c4 * 4 + 2][r] = va.z; As[c4 * 4 + 3][r] = va.w;
            float4 vb = *(const float4*)(Bm + (size_t)(bn + r) * K + kc + c4 * 4);
            Bs[c4 * 4 + 0][r] = vb.x; Bs[c4 * 4 + 1][r] = vb.y;
            Bs[c4 * 4 + 2][r] = vb.z; Bs[c4 * 4 + 3][r] = vb.w;
        }
        __syncthreads();
#pragma unroll
        for (int k = 0; k < BK; k++) {
            float4 a0 = *(const float4*)&As[k][ty * 8];
            float4 a1 = *(const float4*)&As[k][ty * 8 + 4];
            ulonglong2 b0 = *(const ulonglong2*)&Bs[k][tx * 8];
            ulonglong2 b1 = *(const ulonglong2*)&Bs[k][tx * 8 + 4];
            ull bb[4] = { b0.x, b0.y, b1.x, b1.y };
            ull a2[8];
            a2[0] = pack2(a0.x, a0.x); a2[1] = pack2(a0.y, a0.y);
            a2[2] = pack2(a0.z, a0.z); a2[3] = pack2(a0.w, a0.w);
            a2[4] = pack2(a1.x, a1.x); a2[5] = pack2(a1.y, a1.y);
            a2[6] = pack2(a1.z, a1.z); a2[7] = pack2(a1.w, a1.w);
#pragma unroll
            for (int i = 0; i < 8; i++)
#pragma unroll
                for (int j = 0; j < 4; j++)
                    acc2[i][j] = fma2(a2[i], bb[j], acc2[i][j]);
        }
        __syncthreads();
    }

    float bs[8];
#pragma unroll
    for (int j = 0; j < 8; j++) {
        int n = bn + tx * 8 + j;
        bs[j] = bias0[n] + (bias1 ? bias1[n] : 0.0f);
    }
#pragma unroll
    for (int i = 0; i < 8; i++) {
        float acc[8];
#pragma unroll
        for (int j = 0; j < 4; j++)
            unpack2(acc2[i][j], acc[2 * j], acc[2 * j + 1]);
        size_t row = (size_t)(bm + ty * 8 + i) * N + bn + tx * 8;
        float4 v0 = make_float4(acc[0] + bs[0], acc[1] + bs[1],
                                acc[2] + bs[2], acc[3] + bs[3]);
        float4 v1 = make_float4(acc[4] + bs[4], acc[5] + bs[5],
                                acc[6] + bs[6], acc[7] + bs[7]);
        *(float4*)(C + row)     = v0;
        *(float4*)(C + row + 4) = v1;
    }
}

// ---------------- persistent recurrence: 2-group interleave ----------------
// 128 blocks x 512 threads (1/SM). Block bx owns 32 cols n0=(bx>>2)*32 and
// serves TWO batch groups gA=bx&3, gB=gA+4 (8 batches each) with the SAME
// W registers. Virtual steps alternate groups: while one group's barrier /
// store-visibility chain settles, the other group's step computes. Warp w
// owns k-chunk [64w,64w+64); lane l owns column n0+l (32 f32x2 W regs).
#define RBLK 128
#define RTHR 512
#define NW   16
#define KCH  64
#define NB   8                                     // batches per group
#define PARTP 33
#define BUF_F (NW * NB * KCH)                      // 8192 floats = 32KB
#define REC_SMEM ((2 * BUF_F + NW * NB * PARTP) * 4)

__global__ void __launch_bounds__(RTHR, 1)
rnn_recurrence(const float* __restrict__ xp, const float* __restrict__ Whh,
               const float* __restrict__ h0, float* __restrict__ hs)
{
    extern __shared__ float sm[];
    float* bufs[2] = { sm, sm + BUF_F };
    float* part    = sm + 2 * BUF_F;    // [16][8][PARTP]

    const int t  = threadIdx.x;
    const int bx = blockIdx.x;
    const int n0 = (bx >> 2) * 32;      // first col of this block
    const int gA = bx & 3;              // groups gA and gA+4
    const int w  = t >> 5;              // warp: k-chunk owner
    const int l  = t & 31;              // lane: column owner
    const int k0 = w * KCH;

    // reduce mapping (threads 0..255): one output each
    const int eb = (t & 255) >> 5;      // batch 0..7
    const int ec = t & 31;              // col 0..31

    // Load this lane's W_hh column-slice into registers (once).
    ull Wreg[32];
    {
        const float2* wrow = (const float2*)(Whh + (size_t)(n0 + l) * H_ + k0);
#pragma unroll
        for (int j = 0; j < 32; j++) {
            float2 v = wrow[j];
            Wreg[j] = pack2(v.x, v.y);
        }
    }

    const uint32_t buf_u32[2] = { smem_u32(bufs[0]) + (uint32_t)(w * NB * KCH) * 4,
                                  smem_u32(bufs[1]) + (uint32_t)(w * NB * KCH) * 4 };

    // ---- prologue: stage (gA, s=0) from h0 into buf0 ----
    {
        const float* srcb = h0 + (size_t)(gA * NB) * H_ + k0;
#pragma unroll
        for (int i = 0; i < 4; i++) {
            int id = i * 32 + l;        // 0..127
            int r  = id >> 4;           // batch row 0..7
            int c  = id & 15;           // float4 col 0..15
            cp16(buf_u32[0] + (uint32_t)(r * KCH + c * 4) * 4,
                 srcb + (size_t)r * H_ + c * 4);
        }
        CP_COMMIT();
    }

    for (int v = 0; v < 2 * S_; v++) {
        const int g  = (v & 1) ? (gA + 4) : gA;
        const int s  = v >> 1;
        const int gn = ((v + 1) & 1) ? (gA + 4) : gA;
        const int sn = (v + 1) >> 1;
        const float* bufc = bufs[v & 1];

        if (v < 2 * S_ - 1) {
            // wait for h_{gn}(sn-1) (produced at v-1), then stage it
            if (sn > 0) {
                volatile unsigned* bar = (volatile unsigned*)&g_bar8[gn * 32];
                const unsigned tgt = 32u * (unsigned)sn;
                if (l == 0) {
                    unsigned cnt;
                    do {
                        asm volatile("ld.acquire.gpu.global.u32 %0, [%1];"
                                     : "=r"(cnt) : "l"(bar) : "memory");
                    } while (cnt < tgt);
                }
                __syncwarp();
            }
            {
                const float* srcb;
                size_t rstride;
                if (sn == 0) {
                    srcb = h0 + (size_t)(gn * NB) * H_ + k0;
                    rstride = H_;
                } else {
                    srcb = hs + ((size_t)(gn * NB) * S_ + (sn - 1)) * H_ + k0;
                    rstride = (size_t)S_ * H_;
                }
                const uint32_t base = buf_u32[(v + 1) & 1];
#pragma unroll
                for (int i = 0; i < 4; i++) {
                    int id = i * 32 + l;
                    int r  = id >> 4;
                    int c  = id & 15;
                    cp16(base + (uint32_t)(r * KCH + c * 4) * 4,
                         srcb + (size_t)r * rstride + c * 4);
                }
                CP_COMMIT();
            }
            CP_WAIT(1);       // current step's data (committed at v-1) ready
        } else {
            CP_WAIT(0);
        }
        __syncwarp();

        // prefetch xp for this step's epilogue (overlaps compute)
        size_t oidx = 0;
        float xv = 0.0f;
        if (t < 256) {
            oidx = ((size_t)(g * NB + eb) * S_ + s) * H_ + n0 + ec;
            xv = __ldg(xp + oidx);
        }

        // compute partials: h broadcast from smem, W in registers
#pragma unroll
        for (int b = 0; b < NB; b++) {
            const ulonglong2* hrow = (const ulonglong2*)(bufc + (w * NB + b) * KCH);
            ull a0 = 0, a1 = 0, a2 = 0, a3 = 0;
#pragma unroll
            for (int j = 0; j < 16; j += 2) {
                ulonglong2 h2a = hrow[j];
                ulonglong2 h2b = hrow[j + 1];
                a0 = fma2(h2a.x, Wreg[2 * j + 0], a0);
                a1 = fma2(h2a.y, Wreg[2 * j + 1], a1);
                a2 = fma2(h2b.x, Wreg[2 * j + 2], a2);
                a3 = fma2(h2b.y, Wreg[2 * j + 3], a3);
            }
            float x0, x1;
            unpack2(add2(add2(a0, a1), add2(a2, a3)), x0, x1);
            part[(w * NB + b) * PARTP + l] = x0 + x1;
        }
        __syncthreads();

        // reduce 16 k-partials, add xp, tanh, store (threads 0..255)
        if (t < 256) {
            float ssum = 0.f;
#pragma unroll
            for (int w16 = 0; w16 < NW; w16++)
                ssum += part[(w16 * NB + eb) * PARTP + ec];
            hs[oidx] = tanh_acc(ssum + xv);
        }
        __syncthreads();

        // release-arrive on this group's barrier
        if (t == 0) {
            asm volatile("red.release.gpu.global.add.u32 [%0], %1;"
                         :: "l"(&g_bar8[g * 32]), "r"(1u) : "memory");
        }
    }
}

// last_hidden[b][k] = hs[b][S-1][k]
__global__ void copy_last(const float* __restrict__ hs, float* __restrict__ out)
{
    int i = blockIdx.x * 256 + threadIdx.x;
    int b = i >> 10, k = i & (H_ - 1);
    out[i] = hs[((size_t)b * S_ + (S_ - 1)) * H_ + k];
}

// ---------------- launch ----------------
extern "C" void kernel_launch(void* const* d_in, const int* in_sizes, int n_in,
                              void* d_out, int out_size)
{
    const float* inputs = (const float*)d_in[0];
    const float* h0     = (const float*)d_in[1];
    const float* W_ih   = (const float*)d_in[2];
    const float* b_ih   = (const float*)d_in[3];
    const float* W_hh   = (const float*)d_in[4];
    const float* b_hh   = (const float*)d_in[5];
    const float* W_ho   = (const float*)d_in[6];
    const float* b_ho   = (const float*)d_in[7];
    float* out = (float*)d_out;

    float *xp, *hs;
    cudaGetSymbolAddress((void**)&xp, g_xp);
    cudaGetSymbolAddress((void**)&hs, g_hs);

    cudaFuncSetAttribute(rnn_recurrence,
                         cudaFuncAttributeMaxDynamicSharedMemorySize, REC_SMEM);

    zero_bar<<<1, 256>>>();

    // xp = inputs @ W_ih^T + b_ih + b_hh   (M=B*S, N=H, K=I)
    dim3 g1(H_ / 128, (B_ * S_) / 128);
    gemm_nt_bias<<<g1, 256>>>(inputs, W_ih, b_ih, b_hh, xp, B_ * S_, H_, I_);

    // sequential scan, persistent kernel (2-group interleave)
    rnn_recurrence<<<RBLK, RTHR, REC_SMEM>>>(xp, W_hh, h0, hs);

    // outputs = hs @ W_ho^T + b_ho         (M=B*S, N=O, K=H)
    dim3 g2(O_ / 128, (B_ * S_) / 128);
    gemm_nt_bias<<<g2, 256>>>(hs, W_ho, b_ho, nullptr, out, B_ * S_, O_, H_);

    // last_hidden appended after outputs
    copy_last<<<(B_ * H_) / 256, 256>>>(hs, out + (size_t)B_ * S_ * O_);
}